// round 2
// baseline (speedup 1.0000x reference)
#include <cuda_runtime.h>
#include <cstdint>
#include <math.h>

// ---------------------------------------------------------------------------
// SO3Reparameterize fused kernel, round 2.
// Changes vs R1 (100us, DRAM 33%, occ 11%, issue 19%):
//   * 448 threads (14 warps), 1 row/thread  -> 2x issue capacity
//   * CHUNK_K 32 (32 barriers instead of 64), 3-stage cp.async ring
//   * prefetch issued immediately after barrier (before compute)
//   * staging addresses recomputed affinely (frees ~45 regs)
// ---------------------------------------------------------------------------

#define B_ROWS   65536
#define D_IN     1024
#define NBLK     148
#define NTHR     448
#define ROWS_CAP 448
#define CHUNK_K  32
#define NCHUNK   (D_IN / CHUNK_K)     // 32
#define NPAIR    (CHUNK_K / 2)        // 16
#define ROW_F    34                   // 32 + 2 pad -> conflict-free LDS.64
#define STAGES   3
#define SLOT_F   (ROWS_CAP * ROW_F)   // 15232 floats
#define SLOT_B   (SLOT_F * 4)         // 60928 B
#define WP_U64   (512 * 10)           // 512 k-pairs x (9 coeffs + pad) f32x2
#define WP_BYTES (WP_U64 * 8)         // 40960 B
#define SMEM_BYTES (WP_BYTES + STAGES * SLOT_B)   // 223744 B  (< 227KB)

typedef unsigned long long ull;

__device__ __forceinline__ void fma2(ull &acc, ull x, ull w) {
    asm("fma.rn.f32x2 %0, %1, %2, %0;" : "+l"(acc) : "l"(x), "l"(w));
}
__device__ __forceinline__ ull pack2(float lo, float hi) {
    ull r; asm("mov.b64 %0, {%1, %2};" : "=l"(r) : "f"(lo), "f"(hi)); return r;
}
__device__ __forceinline__ float2 unpack2(ull v) {
    float2 f; asm("mov.b64 {%0, %1}, %2;" : "=f"(f.x), "=f"(f.y) : "l"(v)); return f;
}
__device__ __forceinline__ void cp8(uint32_t dst, const void* src) {
    asm volatile("cp.async.ca.shared.global [%0], [%1], 8;" :: "r"(dst), "l"(src) : "memory");
}
__device__ __forceinline__ void cp_commit() {
    asm volatile("cp.async.commit_group;" ::: "memory");
}
__device__ __forceinline__ void cp_wait1() {
    asm volatile("cp.async.wait_group 1;" ::: "memory");
}

__device__ __forceinline__ float softplus_f(float x) {
    return fmaxf(x, 0.0f) + log1pf(expf(-fabsf(x)));
}

__device__ __forceinline__ void rodrigues(float vx, float vy, float vz, float R[9]) {
    float n2  = vx * vx + vy * vy + vz * vz;
    float th  = sqrtf(n2);
    float inv = 1.0f / th;                 // matches reference (no zero guard)
    float x = vx * inv, y = vy * inv, z = vz * inv;
    float s, c;
    sincosf(th, &s, &c);
    float C = 1.0f - c;
    float xC = x * C, yC = y * C, zC = z * C;
    float xs_ = x * s, ys_ = y * s, zs_ = z * s;
    R[0] = c + x * xC;  R[1] = x * yC - zs_; R[2] = x * zC + ys_;
    R[3] = x * yC + zs_; R[4] = c + y * yC;  R[5] = y * zC - xs_;
    R[6] = x * zC - ys_; R[7] = y * zC + xs_; R[8] = c + z * zC;
}

__global__ void __launch_bounds__(NTHR, 1)
so3_kernel(const float* __restrict__ x,   const float* __restrict__ eps,
           const float* __restrict__ Wmu, const float* __restrict__ bmu,
           const float* __restrict__ Wd,  const float* __restrict__ bd,
           const float* __restrict__ Wl,  const float* __restrict__ bl,
           float* __restrict__ out)
{
    extern __shared__ unsigned char smem[];
    ull*   Wp = (ull*)smem;                       // [512 k-pairs][10] f32x2
    float* xs = (float*)(smem + WP_BYTES);        // [STAGES][ROWS_CAP][ROW_F]
    uint32_t xs_s = (uint32_t)__cvta_generic_to_shared(xs);

    const int t = threadIdx.x;
    const int b = blockIdx.x;
    const int start = (int)(((long long)b * B_ROWS) / NBLK);
    const int end   = (int)(((long long)(b + 1) * B_ROWS) / NBLK);
    const int nrows = end - start;                // 442 or 443 (<= 448)

    // ---- staging geometry: thread covers 8B-unit `pos` of rows r0 + 28j
    const int pos = t & 15;                       // 16 x 8B = 128B per row chunk
    const int r0  = t >> 4;                       // 0..27
    const float* sbase = x + (size_t)(start + r0) * D_IN + pos * 2;
    // wrap mask: rows past B_ROWS-1 wrap back 448 rows (duplicates, harmless)
    unsigned wmask = 0;
#pragma unroll
    for (int j = 0; j < 16; ++j)
        if (start + r0 + 28 * j >= B_ROWS) wmask |= (1u << j);
    const uint32_t sobase = xs_s + (uint32_t)((r0 * ROW_F + pos * 2) * 4);

#define STAGE(nc_, slot_)                                                     \
    do {                                                                      \
        uint32_t sb_ = sobase + (uint32_t)(slot_) * SLOT_B;                   \
        const float* gb_ = sbase + (size_t)(nc_) * CHUNK_K;                   \
        _Pragma("unroll")                                                     \
        for (int j_ = 0; j_ < 16; ++j_) {                                     \
            const float* p_ = gb_ + (size_t)j_ * (28 * D_IN);                 \
            if ((wmask >> j_) & 1) p_ -= (size_t)448 * D_IN;                  \
            cp8(sb_ + j_ * (28 * ROW_F * 4), p_);                             \
        }                                                                     \
    } while (0)

    // ---- prologue: chunks 0 and 1
    STAGE(0, 0); cp_commit();
    STAGE(1, 1); cp_commit();

    // ---- pack W into smem as k-pair f32x2 (overlaps prologue cp.asyncs)
    for (int i = t; i < WP_U64; i += NTHR) {
        int p = i / 10, c = i % 10;
        int k0 = 2 * p;
        float lo = 0.0f, hi = 0.0f;
        if (c < 3)      { lo = __ldg(Wmu + k0 * 3 + c);       hi = __ldg(Wmu + (k0 + 1) * 3 + c); }
        else if (c < 6) { lo = __ldg(Wd  + k0 * 3 + (c - 3)); hi = __ldg(Wd  + (k0 + 1) * 3 + (c - 3)); }
        else if (c < 9) { lo = __ldg(Wl  + k0 * 3 + (c - 6)); hi = __ldg(Wl  + (k0 + 1) * 3 + (c - 6)); }
        Wp[i] = pack2(lo, hi);
    }

    ull acc[9];
#pragma unroll
    for (int c = 0; c < 9; ++c) acc[c] = 0ull;

    // ---- main loop: 32 chunks, 3-slot ring, prefetch-before-compute
    int slot_c = 0;   // slot holding chunk ch
    int slot_p = 2;   // slot to prefetch chunk ch+2 into (held chunk ch-1)
    for (int ch = 0; ch < NCHUNK; ++ch) {
        cp_wait1();                  // chunk ch landed (this thread's copies)
        __syncthreads();             // ...all threads' copies visible; ch-1 fully consumed

        const int nc = ch + STAGES - 1;
        if (nc < NCHUNK) STAGE(nc, slot_p);
        cp_commit();                 // empty groups keep wait arithmetic uniform

        const float* pa = xs + slot_c * SLOT_F + t * ROW_F;
        const ull* wrow = Wp + (size_t)ch * NPAIR * 10;

#pragma unroll
        for (int p = 0; p < NPAIR; ++p) {
            ull xa = *(const ull*)(pa + 2 * p);                            // LDS.64
            ulonglong2 w01 = *(const ulonglong2*)(wrow + p * 10 + 0);      // broadcast LDS.128
            ulonglong2 w23 = *(const ulonglong2*)(wrow + p * 10 + 2);
            ulonglong2 w45 = *(const ulonglong2*)(wrow + p * 10 + 4);
            ulonglong2 w67 = *(const ulonglong2*)(wrow + p * 10 + 6);
            ull        w8  = wrow[p * 10 + 8];
            fma2(acc[0], xa, w01.x);
            fma2(acc[1], xa, w01.y);
            fma2(acc[2], xa, w23.x);
            fma2(acc[3], xa, w23.y);
            fma2(acc[4], xa, w45.x);
            fma2(acc[5], xa, w45.y);
            fma2(acc[6], xa, w67.x);
            fma2(acc[7], xa, w67.y);
            fma2(acc[8], xa, w8);
        }

        slot_c = (slot_c == STAGES - 1) ? 0 : slot_c + 1;
        slot_p = (slot_p == STAGES - 1) ? 0 : slot_p + 1;
    }
#undef STAGE

    // ---- epilogue: per-row SO(3) math, pure registers
    float y[9];
#pragma unroll
    for (int c = 0; c < 9; ++c) { float2 f = unpack2(acc[c]); y[c] = f.x + f.y; }

    if (t < nrows) {
        const int row = start + t;
        float mux = y[0] + __ldg(bmu + 0);
        float muy = y[1] + __ldg(bmu + 1);
        float muz = y[2] + __ldg(bmu + 2);
        float d0 = softplus_f(y[3] + __ldg(bd + 0));
        float d1 = softplus_f(y[4] + __ldg(bd + 1));
        float d2 = softplus_f(y[5] + __ldg(bd + 2));
        float l0 = y[6] + __ldg(bl + 0);
        float l1 = y[7] + __ldg(bl + 1);
        float l2 = y[8] + __ldg(bl + 2);

        float e0 = __ldg(eps + (size_t)row * 3 + 0);
        float e1 = __ldg(eps + (size_t)row * 3 + 1);
        float e2 = __ldg(eps + (size_t)row * 3 + 2);

        float s0 = sqrtf(d0) * e0;
        float s1 = sqrtf(d1) * e1;
        float s2 = sqrtf(d2) * e2;

        float v0 = s0;
        float v1 = l0 * s0 + s1;
        float v2 = l1 * s0 + l2 * s1 + s2;

        float Rm[9], Rv[9];
        rodrigues(mux, muy, muz, Rm);
        rodrigues(v0, v1, v2, Rv);

        float* o = out + (size_t)row * 9;
#pragma unroll
        for (int i = 0; i < 3; ++i) {
#pragma unroll
            for (int j = 0; j < 3; ++j) {
                o[i * 3 + j] = Rm[i * 3 + 0] * Rv[0 * 3 + j]
                             + Rm[i * 3 + 1] * Rv[1 * 3 + j]
                             + Rm[i * 3 + 2] * Rv[2 * 3 + j];
            }
        }
    }
}

extern "C" void kernel_launch(void* const* d_in, const int* in_sizes, int n_in,
                              void* d_out, int out_size)
{
    const float* x   = (const float*)d_in[0];
    const float* eps = (const float*)d_in[1];
    const float* Wmu = (const float*)d_in[2];
    const float* bmu = (const float*)d_in[3];
    const float* Wd  = (const float*)d_in[4];
    const float* bd  = (const float*)d_in[5];
    const float* Wl  = (const float*)d_in[6];
    const float* bl  = (const float*)d_in[7];

    cudaFuncSetAttribute(so3_kernel, cudaFuncAttributeMaxDynamicSharedMemorySize, SMEM_BYTES);
    so3_kernel<<<NBLK, NTHR, SMEM_BYTES>>>(x, eps, Wmu, bmu, Wd, bd, Wl, bl, (float*)d_out);
}